// round 14
// baseline (speedup 1.0000x reference)
#include <cuda_runtime.h>
#include <cuda_fp16.h>
#include <cstdint>
#include <math.h>

// ---------------------------------------------------------------------------
// Problem constants
// ---------------------------------------------------------------------------
#define BS      2
#define QLEN    21760            // 128^2 + 64^2 + 32^2 + 16^2
#define MROWS   (BS * QLEN)      // 43520
#define CDIM    256
#define HEADS   8
#define DHEAD   32
#define LEVELS  4
#define POINTS  4
#define NOA     384              // concat: 256 offsets + 128 attn logits

// ---------------------------------------------------------------------------
// Scratch (static device globals)
// ---------------------------------------------------------------------------
__device__ __half g_val_h[MROWS * CDIM];      // value @ W_v + b_v (fp16 table, [m][c])
__device__ float  g_oa  [MROWS * NOA];        // [m][0:256]=offsets, [256:384]=logits
__device__ __half g_v16 [MROWS * CDIM];       // value fp16 (GEMM A)
__device__ __half g_q16 [MROWS * CDIM];       // query fp16 (GEMM A)
__device__ __half g_s16 [MROWS * CDIM];       // sampled fp16 (GEMM A)

// Transposed weights [N, K=256] fp16 (single precision pass)
__device__ __half g_wv [CDIM * CDIM];
__device__ __half g_oaw[NOA  * CDIM];
__device__ __half g_wu [CDIM * CDIM];
__device__ float  g_bias_oa[NOA];

// ---------------------------------------------------------------------------
// Helpers
// ---------------------------------------------------------------------------
__device__ __forceinline__ uint32_t smem_u32(const void* p) {
    uint32_t a;
    asm("{ .reg .u64 t; cvta.to.shared.u64 t, %1; cvt.u32.u64 %0, t; }" : "=r"(a) : "l"(p));
    return a;
}
#define SMEM_SWZ64(off) ((off) ^ (((off) >> 3) & 0x30))

__device__ __forceinline__ void ldsm4(uint32_t& r0, uint32_t& r1, uint32_t& r2, uint32_t& r3,
                                      uint32_t addr) {
    asm volatile("ldmatrix.sync.aligned.m8n8.x4.shared.b16 {%0,%1,%2,%3}, [%4];"
                 : "=r"(r0), "=r"(r1), "=r"(r2), "=r"(r3) : "r"(addr));
}
__device__ __forceinline__ void mma_f16(float* d, const uint32_t* a, const uint32_t* b) {
    asm volatile(
        "mma.sync.aligned.m16n8k16.row.col.f32.f16.f16.f32 "
        "{%0,%1,%2,%3}, {%4,%5,%6,%7}, {%8,%9}, {%0,%1,%2,%3};"
        : "+f"(d[0]), "+f"(d[1]), "+f"(d[2]), "+f"(d[3])
        : "r"(a[0]), "r"(a[1]), "r"(a[2]), "r"(a[3]), "r"(b[0]), "r"(b[1]));
}
#define CP_ASYNC16(dst_u32, src_ptr) \
    asm volatile("cp.async.cg.shared.global [%0], [%1], 16;" :: "r"(dst_u32), "l"(src_ptr))
#define CP_COMMIT()  asm volatile("cp.async.commit_group;" ::: "memory")
#define CP_WAIT1()   asm volatile("cp.async.wait_group 1;" ::: "memory")
#define CP_WAIT0()   asm volatile("cp.async.wait_group 0;" ::: "memory")

// ---------------------------------------------------------------------------
// Prep: fp32 -> fp16 conversion for value & query (GEMM A operands)
// ---------------------------------------------------------------------------
__global__ void to_half_kernel(const float* __restrict__ value,
                               const float* __restrict__ query,
                               __half* __restrict__ vh, __half* __restrict__ qh, int n4)
{
    int i = blockIdx.x * blockDim.x + threadIdx.x;
    if (i >= n4) return;
    const float* x = blockIdx.y ? query : value;
    __half* o = blockIdx.y ? qh : vh;
    float4 v = ((const float4*)x)[i];
    __half2 h01 = __floats2half2_rn(v.x, v.y);
    __half2 h23 = __floats2half2_rn(v.z, v.w);
    uint2 pk; pk.x = *(uint32_t*)&h01; pk.y = *(uint32_t*)&h23;
    ((uint2*)o)[i] = pk;
}

// Weights: transpose to [N,256] fp16. which=0: W_v, 1: [W_off|W_attn], 2: W_out
__global__ void prep_weights(const float* __restrict__ Wv,
                             const float* __restrict__ Woff,
                             const float* __restrict__ Wattn,
                             const float* __restrict__ Wout,
                             const float* __restrict__ b_off,
                             const float* __restrict__ b_attn,
                             __half* __restrict__ wv,
                             __half* __restrict__ woa,
                             __half* __restrict__ wu,
                             float* __restrict__ bias_oa)
{
    const int which = blockIdx.y;
    const int n = blockIdx.x;
    const int k = threadIdx.x;
    float v; __half* t;
    if (which == 0) {
        if (n >= CDIM) return;
        v = Wv[k * CDIM + n]; t = wv;
    } else if (which == 1) {
        v = (n < 256) ? Woff[k * 256 + n] : Wattn[k * 128 + (n - 256)];
        t = woa;
        if (k == 0) bias_oa[n] = (n < 256) ? b_off[n] : b_attn[n - 256];
    } else {
        if (n >= CDIM) return;
        v = Wout[k * CDIM + n]; t = wu;
    }
    t[n * 256 + k] = __float2half_rn(v);
}

// ---------------------------------------------------------------------------
// HMMA GEMM (fp16, single-pass): C[M,N] = A[M,256] @ B[N,256]^T + bias
// CTA 128x128, 8 warps (4x2). K chunks of 32, 3-stage cp.async pipeline,
// SW64 smem. Out: fp32 C, or fp16 Ch ([m][Ncols] row-major).
// ---------------------------------------------------------------------------
#define STAGE_BYTES 16384                      // A 8KB + B 8KB
#define GEMM_SMEM_BYTES (3 * STAGE_BYTES)

__global__ __launch_bounds__(256, 2)
void mma_gemm(const __half* __restrict__ A, const __half* __restrict__ B,
              const float* __restrict__ bias, float* __restrict__ C,
              __half* __restrict__ Ch, int Ncols)
{
    extern __shared__ char smem[];
    const uint32_t sb = smem_u32(smem);

    const int tid  = threadIdx.x;
    const int lane = tid & 31;
    const int wid  = tid >> 5;
    const int wm   = wid & 3;
    const int wn   = wid >> 2;
    const int mtile = blockIdx.x * 128;
    const int ntile = blockIdx.y * 128;

    float acc[2][8][4];
#pragma unroll
    for (int i = 0; i < 2; i++)
#pragma unroll
        for (int j = 0; j < 8; j++)
#pragma unroll
            for (int k = 0; k < 4; k++) acc[i][j][k] = 0.f;

    const int a_row = wm * 32 + (lane & 7) + ((lane >> 3) & 1) * 8;
    const int a_sg  = (lane >> 4);
    const int b_row = wn * 64 + (lane & 7) + (lane >> 4) * 8;
    const int b_sg  = ((lane >> 3) & 1);

#define LOAD_STAGE(cc, buf) do {                                                   \
    const uint32_t st = sb + (buf) * STAGE_BYTES;                                  \
    const int kc = (cc) * 32;                                                      \
    _Pragma("unroll")                                                              \
    for (int it = 0; it < 2; it++) {                                               \
        int idx = it * 256 + tid;                                                  \
        int row = idx >> 2, seg = idx & 3;                                         \
        uint32_t so = SMEM_SWZ64((uint32_t)(row * 64 + seg * 16));                 \
        size_t ga = (size_t)(mtile + row) * 256 + kc + seg * 8;                    \
        size_t gb = (size_t)(ntile + row) * 256 + kc + seg * 8;                    \
        CP_ASYNC16(st + so,        A + ga);                                        \
        CP_ASYNC16(st + 8192 + so, B + gb);                                        \
    }                                                                              \
} while (0)

    // prologue: 2 stages in flight
    LOAD_STAGE(0, 0);
    CP_COMMIT();
    LOAD_STAGE(1, 1);
    CP_COMMIT();

    int cbuf = 0;
#pragma unroll 1
    for (int c = 0; c < 8; c++) {
        if (c < 7) CP_WAIT1(); else CP_WAIT0();
        __syncthreads();

        if (c < 6) {
            const int lbuf = (cbuf + 2 >= 3) ? cbuf + 2 - 3 : cbuf + 2;
            LOAD_STAGE(c + 2, lbuf);
            CP_COMMIT();
        }

        const uint32_t st = sb + cbuf * STAGE_BYTES;
        const uint32_t sA = st, sB = st + 8192;

#pragma unroll
        for (int ks = 0; ks < 2; ks++) {
            uint32_t a[2][4];
#pragma unroll
            for (int mt = 0; mt < 2; mt++) {
                uint32_t off = SMEM_SWZ64((uint32_t)((a_row + mt * 16) * 64 +
                                                     (a_sg + ks * 2) * 16));
                ldsm4(a[mt][0], a[mt][1], a[mt][2], a[mt][3], sA + off);
            }
#pragma unroll
            for (int nt2 = 0; nt2 < 4; nt2++) {
                uint32_t off = SMEM_SWZ64((uint32_t)((b_row + nt2 * 16) * 64 +
                                                     (b_sg + ks * 2) * 16));
                uint32_t bfr[4];
                ldsm4(bfr[0], bfr[1], bfr[2], bfr[3], sB + off);
#pragma unroll
                for (int mt = 0; mt < 2; mt++)
#pragma unroll
                    for (int half = 0; half < 2; half++)
                        mma_f16(acc[mt][nt2 * 2 + half], a[mt], &bfr[half * 2]);
            }
        }
        cbuf = (cbuf + 1 >= 3) ? 0 : cbuf + 1;
    }
#undef LOAD_STAGE

    if (Ch) {
#pragma unroll
        for (int mt = 0; mt < 2; mt++) {
            const int r0 = mtile + wm * 32 + mt * 16 + (lane >> 2);
#pragma unroll
            for (int nt = 0; nt < 8; nt++) {
                const int cc = ntile + wn * 64 + nt * 8 + (lane & 3) * 2;
                const float bx = __ldg(bias + cc), by = __ldg(bias + cc + 1);
                __half2 h0 = __floats2half2_rn(acc[mt][nt][0] + bx, acc[mt][nt][1] + by);
                __half2 h1 = __floats2half2_rn(acc[mt][nt][2] + bx, acc[mt][nt][3] + by);
                *(__half2*)&Ch[(size_t)r0       * Ncols + cc] = h0;
                *(__half2*)&Ch[(size_t)(r0 + 8) * Ncols + cc] = h1;
            }
        }
    } else {
#pragma unroll
        for (int mt = 0; mt < 2; mt++) {
            const int r0 = mtile + wm * 32 + mt * 16 + (lane >> 2);
#pragma unroll
            for (int nt = 0; nt < 8; nt++) {
                const int cc = ntile + wn * 64 + nt * 8 + (lane & 3) * 2;
                const float bx = __ldg(bias + cc), by = __ldg(bias + cc + 1);
                float2 o0 = {acc[mt][nt][0] + bx, acc[mt][nt][1] + by};
                float2 o1 = {acc[mt][nt][2] + bx, acc[mt][nt][3] + by};
                *(float2*)&C[(size_t)r0       * Ncols + cc] = o0;
                *(float2*)&C[(size_t)(r0 + 8) * Ncols + cc] = o1;
            }
        }
    }
}

// ---------------------------------------------------------------------------
// Deformable sampling v3 (proven): warp = head; lane -> (group g = lane>>2,
// octet c4 = lane&3). 8 groups process 8 corners per warp-instruction; lane
// gathers 8 channels via LDG.128. 512-thread blocks: 2 queries per block.
// ---------------------------------------------------------------------------
__global__ __launch_bounds__(512)
void sample_kernel(const __half* __restrict__ valh,
                   const float* __restrict__ oa,
                   const float* __restrict__ ref,
                   __half* __restrict__ sout)
{
    const int q    = blockIdx.x * 2 + (threadIdx.x >> 8);
    const int b    = blockIdx.y;
    const int m    = b * QLEN + q;
    const int tid  = threadIdx.x & 255;
    const int head = tid >> 5;
    const int lane = threadIdx.x & 31;
    const int g    = lane >> 2;        // 8 groups of 4 lanes
    const int c4   = lane & 3;         // channel octet
    const int l    = g >> 1;           // level
    const int h    = g & 1;            // point-half

    // --- softmax over this head's 16 logits ---
    const float* row = oa + (size_t)m * NOA;
    float lg = __ldg(&row[256 + head * 16 + (lane & 15)]);
    float mx = lg;
#pragma unroll
    for (int d = 1; d < 16; d <<= 1) mx = fmaxf(mx, __shfl_xor_sync(~0u, mx, d));
    float e = __expf(lg - mx);
    float s = e;
#pragma unroll
    for (int d = 1; d < 16; d <<= 1) s += __shfl_xor_sync(~0u, s, d);
    const float a_all = e / s;

    const float ov = __ldg(&row[head * 32 + lane]);
    const float rv = __ldg(&ref[(size_t)m * (LEVELS * 2) + (lane & 7)]);

    const int   Wl = 128 >> l;
    const float Wf = (float)Wl;
    const int   start = (65536 - (65536 >> (2 * l))) / 3;

    const float rx = __shfl_sync(~0u, rv, 2 * l);
    const float ry = __shfl_sync(~0u, rv, 2 * l + 1);

    const __half* valb = valh + ((size_t)b * QLEN + start) * CDIM + head * DHEAD + c4 * 8;

    float acc[8];
#pragma unroll
    for (int i = 0; i < 8; i++) acc[i] = 0.f;

#pragma unroll
    for (int j = 0; j < 2; j++) {
        const int lp = l * 4 + h * 2 + j;
        const float ox = __shfl_sync(~0u, ov, 2 * lp);
        const float oy = __shfl_sync(~0u, ov, 2 * lp + 1);
        const float a  = __shfl_sync(~0u, a_all, lp);

        const float x = fmaf(rx, Wf, ox) - 0.5f;
        const float y = fmaf(ry, Wf, oy) - 0.5f;
        const float x0f = floorf(x), y0f = floorf(y);
        const int   x0 = (int)x0f,  y0 = (int)y0f;
        const float fx = x - x0f,   fy = y - y0f;

#pragma unroll
        for (int dy = 0; dy < 2; dy++) {
            const int  yi = y0 + dy;
            const bool vy = (yi >= 0) && (yi < Wl);
            const int  yc = min(max(yi, 0), Wl - 1);
            const float wy = (dy ? fy : 1.f - fy) * a;
#pragma unroll
            for (int dx = 0; dx < 2; dx++) {
                const int  xi = x0 + dx;
                const bool vx = (xi >= 0) && (xi < Wl);
                const int  xc = min(max(xi, 0), Wl - 1);
                const float w = (vx && vy) ? (dx ? fx : 1.f - fx) * wy : 0.f;

                const uint4 raw = __ldg((const uint4*)&valb[(size_t)(yc * Wl + xc) * CDIM]);
                const float2 f0 = __half22float2(*(const __half2*)&raw.x);
                const float2 f1 = __half22float2(*(const __half2*)&raw.y);
                const float2 f2 = __half22float2(*(const __half2*)&raw.z);
                const float2 f3 = __half22float2(*(const __half2*)&raw.w);
                acc[0] = fmaf(w, f0.x, acc[0]);
                acc[1] = fmaf(w, f0.y, acc[1]);
                acc[2] = fmaf(w, f1.x, acc[2]);
                acc[3] = fmaf(w, f1.y, acc[3]);
                acc[4] = fmaf(w, f2.x, acc[4]);
                acc[5] = fmaf(w, f2.y, acc[5]);
                acc[6] = fmaf(w, f3.x, acc[6]);
                acc[7] = fmaf(w, f3.y, acc[7]);
            }
        }
    }

#pragma unroll
    for (int d = 4; d <= 16; d <<= 1)
#pragma unroll
        for (int i = 0; i < 8; i++)
            acc[i] += __shfl_xor_sync(~0u, acc[i], d);

    if (lane < 4) {
        const size_t o = (size_t)m * CDIM + head * DHEAD + c4 * 8;
        __half2 h0 = __floats2half2_rn(acc[0], acc[1]);
        __half2 h1 = __floats2half2_rn(acc[2], acc[3]);
        __half2 h2 = __floats2half2_rn(acc[4], acc[5]);
        __half2 h3 = __floats2half2_rn(acc[6], acc[7]);
        uint4 pk;
        pk.x = *(uint32_t*)&h0; pk.y = *(uint32_t*)&h1;
        pk.z = *(uint32_t*)&h2; pk.w = *(uint32_t*)&h3;
        *(uint4*)&sout[o] = pk;
    }
}

// ---------------------------------------------------------------------------
// Launch
// ---------------------------------------------------------------------------
extern "C" void kernel_launch(void* const* d_in, const int* in_sizes, int n_in,
                              void* d_out, int out_size)
{
    const float* query  = (const float*)d_in[0];
    const float* value  = (const float*)d_in[1];
    const float* refpts = (const float*)d_in[2];
    const float* W_off  = (const float*)d_in[4];
    const float* b_off  = (const float*)d_in[5];
    const float* W_attn = (const float*)d_in[6];
    const float* b_attn = (const float*)d_in[7];
    const float* W_v    = (const float*)d_in[8];
    const float* b_v    = (const float*)d_in[9];
    const float* W_out  = (const float*)d_in[10];
    const float* b_out  = (const float*)d_in[11];
    float* out = (float*)d_out;

    __half *valh, *v16, *q16, *s16;
    float *oa, *bias_oa;
    cudaGetSymbolAddress((void**)&valh, g_val_h);
    cudaGetSymbolAddress((void**)&oa,   g_oa);
    cudaGetSymbolAddress((void**)&v16,  g_v16);
    cudaGetSymbolAddress((void**)&q16,  g_q16);
    cudaGetSymbolAddress((void**)&s16,  g_s16);
    cudaGetSymbolAddress((void**)&bias_oa, g_bias_oa);
    __half *wv, *woa, *wu;
    cudaGetSymbolAddress((void**)&wv,  g_wv);
    cudaGetSymbolAddress((void**)&woa, g_oaw);
    cudaGetSymbolAddress((void**)&wu,  g_wu);

    cudaFuncSetAttribute(mma_gemm, cudaFuncAttributeMaxDynamicSharedMemorySize, GEMM_SMEM_BYTES);

    // L0: weight transpose + bias concat
    prep_weights<<<dim3(NOA, 3), 256>>>(W_v, W_off, W_attn, W_out, b_off, b_attn,
                                        wv, woa, wu, bias_oa);
    // L1: value/query fp32 -> fp16
    {
        int n4 = MROWS * CDIM / 4;
        to_half_kernel<<<dim3((n4 + 255) / 256, 2), 256>>>(value, query, v16, q16, n4);
    }

    dim3 blk(256);
    dim3 gridV(MROWS / 128, 2);    // N=256
    dim3 gridOA(MROWS / 128, 3);   // N=384
    dim3 gridO(MROWS / 128, 2);    // N=256

    // L2: value projection -> fp16 table [m][256]
    mma_gemm<<<gridV, blk, GEMM_SMEM_BYTES>>>(v16, wv, b_v, nullptr, valh, 256);
    // L3: offsets + attn logits (fused, N=384)
    mma_gemm<<<gridOA, blk, GEMM_SMEM_BYTES>>>(q16, woa, bias_oa, oa, nullptr, NOA);
    // L4: sampler -> fp16 (512-thread blocks, 2 queries each)
    sample_kernel<<<dim3(QLEN / 2, BS), 512>>>(valh, oa, refpts, s16);
    // L5: output projection
    mma_gemm<<<gridO, blk, GEMM_SMEM_BYTES>>>(s16, wu, b_out, out, nullptr, 256);
}

// round 15
// speedup vs baseline: 1.2768x; 1.2768x over previous
#include <cuda_runtime.h>
#include <cuda_fp16.h>
#include <cstdint>
#include <math.h>

// ---------------------------------------------------------------------------
// Problem constants
// ---------------------------------------------------------------------------
#define BS      2
#define QLEN    21760            // 128^2 + 64^2 + 32^2 + 16^2
#define MROWS   (BS * QLEN)      // 43520
#define CDIM    256
#define HEADS   8
#define DHEAD   32
#define LEVELS  4
#define POINTS  4
#define NOA     384              // concat: 256 offsets + 128 attn logits

// ---------------------------------------------------------------------------
// Scratch (static device globals)
// ---------------------------------------------------------------------------
// Head-sliced value table: [b][head][q][32 ch] fp16, 64B per entry.
__device__ __half g_tab[(size_t)BS * HEADS * QLEN * 32];
__device__ float  g_oa  [MROWS * NOA];        // [m][0:256]=offsets, [256:384]=logits
__device__ __half g_v16 [MROWS * CDIM];       // value fp16 (GEMM A)
__device__ __half g_q16 [MROWS * CDIM];       // query fp16 (GEMM A)
__device__ __half g_s16 [MROWS * CDIM];       // sampled fp16 (GEMM A)

// Transposed weights [N, K=256] fp16 hi/lo
__device__ __half g_wv_hi [CDIM * CDIM], g_wv_lo [CDIM * CDIM];
__device__ __half g_oa_hi [NOA  * CDIM], g_oa_lo [NOA  * CDIM];
__device__ __half g_wu_hi [CDIM * CDIM], g_wu_lo [CDIM * CDIM];
__device__ float  g_bias_oa[NOA];

// ---------------------------------------------------------------------------
// Helpers
// ---------------------------------------------------------------------------
__device__ __forceinline__ uint32_t smem_u32(const void* p) {
    uint32_t a;
    asm("{ .reg .u64 t; cvta.to.shared.u64 t, %1; cvt.u32.u64 %0, t; }" : "=r"(a) : "l"(p));
    return a;
}
#define SMEM_SWZ64(off) ((off) ^ (((off) >> 3) & 0x30))

__device__ __forceinline__ void ldsm4(uint32_t& r0, uint32_t& r1, uint32_t& r2, uint32_t& r3,
                                      uint32_t addr) {
    asm volatile("ldmatrix.sync.aligned.m8n8.x4.shared.b16 {%0,%1,%2,%3}, [%4];"
                 : "=r"(r0), "=r"(r1), "=r"(r2), "=r"(r3) : "r"(addr));
}
__device__ __forceinline__ void mma_f16(float* d, const uint32_t* a, const uint32_t* b) {
    asm volatile(
        "mma.sync.aligned.m16n8k16.row.col.f32.f16.f16.f32 "
        "{%0,%1,%2,%3}, {%4,%5,%6,%7}, {%8,%9}, {%0,%1,%2,%3};"
        : "+f"(d[0]), "+f"(d[1]), "+f"(d[2]), "+f"(d[3])
        : "r"(a[0]), "r"(a[1]), "r"(a[2]), "r"(a[3]), "r"(b[0]), "r"(b[1]));
}
#define CP_ASYNC16(dst_u32, src_ptr) \
    asm volatile("cp.async.cg.shared.global [%0], [%1], 16;" :: "r"(dst_u32), "l"(src_ptr))
#define CP_COMMIT()  asm volatile("cp.async.commit_group;" ::: "memory")
#define CP_WAIT1()   asm volatile("cp.async.wait_group 1;" ::: "memory")
#define CP_WAIT0()   asm volatile("cp.async.wait_group 0;" ::: "memory")

// ---------------------------------------------------------------------------
// Prep: fp32 -> fp16 conversion for value & query (GEMM A operands)
// ---------------------------------------------------------------------------
__global__ void to_half_kernel(const float* __restrict__ value,
                               const float* __restrict__ query,
                               __half* __restrict__ vh, __half* __restrict__ qh, int n4)
{
    int i = blockIdx.x * blockDim.x + threadIdx.x;
    if (i >= n4) return;
    const float* x = blockIdx.y ? query : value;
    __half* o = blockIdx.y ? qh : vh;
    float4 v = ((const float4*)x)[i];
    __half2 h01 = __floats2half2_rn(v.x, v.y);
    __half2 h23 = __floats2half2_rn(v.z, v.w);
    uint2 pk; pk.x = *(uint32_t*)&h01; pk.y = *(uint32_t*)&h23;
    ((uint2*)o)[i] = pk;
}

// Weights: transpose + fp16 hi/lo split. which=0: W_v, 1: [W_off|W_attn], 2: W_out
__global__ void prep_weights(const float* __restrict__ Wv,
                             const float* __restrict__ Woff,
                             const float* __restrict__ Wattn,
                             const float* __restrict__ Wout,
                             const float* __restrict__ b_off,
                             const float* __restrict__ b_attn,
                             __half* __restrict__ vh, __half* __restrict__ vl,
                             __half* __restrict__ oh, __half* __restrict__ ol,
                             __half* __restrict__ uh, __half* __restrict__ ul,
                             float* __restrict__ bias_oa)
{
    const int which = blockIdx.y;
    const int n = blockIdx.x;
    const int k = threadIdx.x;
    float v; __half *th, *tl;
    if (which == 0) {
        if (n >= CDIM) return;
        v = Wv[k * CDIM + n]; th = vh; tl = vl;
    } else if (which == 1) {
        v = (n < 256) ? Woff[k * 256 + n] : Wattn[k * 128 + (n - 256)];
        th = oh; tl = ol;
        if (k == 0) bias_oa[n] = (n < 256) ? b_off[n] : b_attn[n - 256];
    } else {
        if (n >= CDIM) return;
        v = Wout[k * CDIM + n]; th = uh; tl = ul;
    }
    __half h = __float2half_rn(v);
    th[n * 256 + k] = h;
    tl[n * 256 + k] = __float2half_rn(v - __half2float(h));
}

// ---------------------------------------------------------------------------
// Shared GEMM main-loop body (R13-proven): 2-pass hi/lo fp16, CTA 128x128,
// K chunks of 32, 3-stage cp.async, SW64 smem. Used by both kernels below.
// ---------------------------------------------------------------------------
#define STAGE_BYTES 24576
#define GEMM_SMEM_BYTES (3 * STAGE_BYTES)

#define GEMM_MAIN_LOOP(A, Bh, Bl)                                                  \
    const uint32_t sb = smem_u32(smem);                                            \
    const int tid  = threadIdx.x;                                                  \
    const int lane = tid & 31;                                                     \
    const int wid  = tid >> 5;                                                     \
    const int wm   = wid & 3;                                                      \
    const int wn   = wid >> 2;                                                     \
    const int mtile = blockIdx.x * 128;                                            \
    const int ntile = blockIdx.y * 128;                                            \
    float acc[2][8][4];                                                            \
    _Pragma("unroll")                                                              \
    for (int i = 0; i < 2; i++)                                                    \
        _Pragma("unroll")                                                          \
        for (int j = 0; j < 8; j++)                                                \
            _Pragma("unroll")                                                      \
            for (int k = 0; k < 4; k++) acc[i][j][k] = 0.f;                        \
    const int a_row = wm * 32 + (lane & 7) + ((lane >> 3) & 1) * 8;                \
    const int a_sg  = (lane >> 4);                                                 \
    const int b_row = wn * 64 + (lane & 7) + (lane >> 4) * 8;                      \
    const int b_sg  = ((lane >> 3) & 1);                                           \
    LOAD_STAGE(0, 0); CP_COMMIT();                                                 \
    LOAD_STAGE(1, 1); CP_COMMIT();                                                 \
    int cbuf = 0;                                                                  \
    _Pragma("unroll 1")                                                            \
    for (int c = 0; c < 8; c++) {                                                  \
        if (c < 7) CP_WAIT1(); else CP_WAIT0();                                    \
        __syncthreads();                                                           \
        if (c < 6) {                                                               \
            const int lbuf = (cbuf + 2 >= 3) ? cbuf + 2 - 3 : cbuf + 2;            \
            LOAD_STAGE(c + 2, lbuf);                                               \
            CP_COMMIT();                                                           \
        }                                                                          \
        const uint32_t st  = sb + cbuf * STAGE_BYTES;                              \
        const uint32_t sA = st, sBh = st + 8192, sBl = st + 16384;                 \
        _Pragma("unroll")                                                          \
        for (int ks = 0; ks < 2; ks++) {                                           \
            uint32_t a[2][4];                                                      \
            _Pragma("unroll")                                                      \
            for (int mt = 0; mt < 2; mt++) {                                       \
                uint32_t off = SMEM_SWZ64((uint32_t)((a_row + mt * 16) * 64 +      \
                                                     (a_sg + ks * 2) * 16));       \
                ldsm4(a[mt][0], a[mt][1], a[mt][2], a[mt][3], sA + off);           \
            }                                                                      \
            _Pragma("unroll")                                                      \
            for (int nt2 = 0; nt2 < 4; nt2++) {                                    \
                uint32_t off = SMEM_SWZ64((uint32_t)((b_row + nt2 * 16) * 64 +     \
                                                     (b_sg + ks * 2) * 16));       \
                uint32_t bh[4], bl[4];                                             \
                ldsm4(bh[0], bh[1], bh[2], bh[3], sBh + off);                      \
                ldsm4(bl[0], bl[1], bl[2], bl[3], sBl + off);                      \
                _Pragma("unroll")                                                  \
                for (int mt = 0; mt < 2; mt++)                                     \
                    _Pragma("unroll")                                              \
                    for (int half = 0; half < 2; half++) {                         \
                        float* a4 = acc[mt][nt2 * 2 + half];                       \
                        mma_f16(a4, a[mt], &bh[half * 2]);                         \
                        mma_f16(a4, a[mt], &bl[half * 2]);                         \
                    }                                                              \
            }                                                                      \
        }                                                                          \
        cbuf = (cbuf + 1 >= 3) ? 0 : cbuf + 1;                                     \
    }

#define LOAD_STAGE(cc, buf) do {                                                   \
    const uint32_t st = sb + (buf) * STAGE_BYTES;                                  \
    const int kc = (cc) * 32;                                                      \
    _Pragma("unroll")                                                              \
    for (int it = 0; it < 2; it++) {                                               \
        int idx = it * 256 + tid;                                                  \
        int row = idx >> 2, seg = idx & 3;                                         \
        uint32_t so = SMEM_SWZ64((uint32_t)(row * 64 + seg * 16));                 \
        size_t ga = (size_t)(mtile + row) * 256 + kc + seg * 8;                    \
        size_t gb = (size_t)(ntile + row) * 256 + kc + seg * 8;                    \
        CP_ASYNC16(st + so,         A  + ga);                                      \
        CP_ASYNC16(st + 8192 + so,  Bh + gb);                                      \
        CP_ASYNC16(st + 16384 + so, Bl + gb);                                      \
    }                                                                              \
} while (0)

// GEMM with fp32 row output (+bias). Used for OA and output projection.
__global__ __launch_bounds__(256, 2)
void mma_gemm(const __half* __restrict__ A,
              const __half* __restrict__ Bh, const __half* __restrict__ Bl,
              const float* __restrict__ bias, float* __restrict__ C, int Ncols)
{
    extern __shared__ char smem[];
    GEMM_MAIN_LOOP(A, Bh, Bl)

#pragma unroll
    for (int mt = 0; mt < 2; mt++) {
        const int r0 = mtile + wm * 32 + mt * 16 + (lane >> 2);
#pragma unroll
        for (int nt = 0; nt < 8; nt++) {
            const int cc = ntile + wn * 64 + nt * 8 + (lane & 3) * 2;
            const float bx = __ldg(bias + cc), by = __ldg(bias + cc + 1);
            float2 o0 = {acc[mt][nt][0] + bx, acc[mt][nt][1] + by};
            float2 o1 = {acc[mt][nt][2] + bx, acc[mt][nt][3] + by};
            *(float2*)&C[(size_t)r0       * Ncols + cc] = o0;
            *(float2*)&C[(size_t)(r0 + 8) * Ncols + cc] = o1;
        }
    }
}

// GEMM with head-sliced fp16 table output (+bias). Used for value projection
// only -- separate kernel so its epilogue cannot poison mma_gemm's registers.
__global__ __launch_bounds__(256, 2)
void mma_gemm_tab(const __half* __restrict__ A,
                  const __half* __restrict__ Bh, const __half* __restrict__ Bl,
                  const float* __restrict__ bias, __half* __restrict__ Tt)
{
    extern __shared__ char smem[];
    GEMM_MAIN_LOOP(A, Bh, Bl)

#pragma unroll
    for (int mt = 0; mt < 2; mt++) {
        const int r0 = mtile + wm * 32 + mt * 16 + (lane >> 2);
#pragma unroll
        for (int nt = 0; nt < 8; nt++) {
            const int cc = ntile + wn * 64 + nt * 8 + (lane & 3) * 2;
            const int h  = cc >> 5, ch = cc & 31;
            const float bx = __ldg(bias + cc), by = __ldg(bias + cc + 1);
            __half2 h0 = __floats2half2_rn(acc[mt][nt][0] + bx, acc[mt][nt][1] + by);
            __half2 h1 = __floats2half2_rn(acc[mt][nt][2] + bx, acc[mt][nt][3] + by);
            {
                const int bq = (r0 >= QLEN) ? 1 : 0;
                const size_t ad = ((size_t)(bq * HEADS + h) * QLEN + (r0 - bq * QLEN)) * 32 + ch;
                *(uint32_t*)&Tt[ad] = *(uint32_t*)&h0;
            }
            {
                const int r1 = r0 + 8;
                const int bq = (r1 >= QLEN) ? 1 : 0;
                const size_t ad = ((size_t)(bq * HEADS + h) * QLEN + (r1 - bq * QLEN)) * 32 + ch;
                *(uint32_t*)&Tt[ad] = *(uint32_t*)&h1;
            }
        }
    }
}
#undef LOAD_STAGE

// ---------------------------------------------------------------------------
// Deformable sampling v3h: identical instruction structure to the proven v3,
// but gathers from the head-sliced table (entry stride 32 halves = 64B).
// Corners x, x+1 are adjacent 64B -> avg 1.5 lines per x-pair (48 lines/warp).
// warp = head; lane -> (group g = lane>>2, octet c4 = lane&3).
// 512-thread blocks: 2 queries per block.
// ---------------------------------------------------------------------------
__global__ __launch_bounds__(512)
void sample_kernel(const __half* __restrict__ tab,
                   const float* __restrict__ oa,
                   const float* __restrict__ ref,
                   __half* __restrict__ sout)
{
    const int q    = blockIdx.x * 2 + (threadIdx.x >> 8);
    const int b    = blockIdx.y;
    const int m    = b * QLEN + q;
    const int tid  = threadIdx.x & 255;
    const int head = tid >> 5;
    const int lane = threadIdx.x & 31;
    const int g    = lane >> 2;        // 8 groups of 4 lanes
    const int c4   = lane & 3;         // channel octet
    const int l    = g >> 1;           // level
    const int h    = g & 1;            // point-half

    // --- softmax over this head's 16 logits ---
    const float* row = oa + (size_t)m * NOA;
    float lg = __ldg(&row[256 + head * 16 + (lane & 15)]);
    float mx = lg;
#pragma unroll
    for (int d = 1; d < 16; d <<= 1) mx = fmaxf(mx, __shfl_xor_sync(~0u, mx, d));
    float e = __expf(lg - mx);
    float s = e;
#pragma unroll
    for (int d = 1; d < 16; d <<= 1) s += __shfl_xor_sync(~0u, s, d);
    const float a_all = e / s;

    const float ov = __ldg(&row[head * 32 + lane]);
    const float rv = __ldg(&ref[(size_t)m * (LEVELS * 2) + (lane & 7)]);

    const int   Wl = 128 >> l;
    const float Wf = (float)Wl;
    const int   start = (65536 - (65536 >> (2 * l))) / 3;

    const float rx = __shfl_sync(~0u, rv, 2 * l);
    const float ry = __shfl_sync(~0u, rv, 2 * l + 1);

    // head-sliced base: [b][head][entry][32ch], this lane reads ch c4*8..+8
    const __half* valb = tab + ((size_t)(b * HEADS + head) * QLEN + start) * 32 + c4 * 8;

    float acc[8];
#pragma unroll
    for (int i = 0; i < 8; i++) acc[i] = 0.f;

#pragma unroll
    for (int j = 0; j < 2; j++) {
        const int lp = l * 4 + h * 2 + j;
        const float ox = __shfl_sync(~0u, ov, 2 * lp);
        const float oy = __shfl_sync(~0u, ov, 2 * lp + 1);
        const float a  = __shfl_sync(~0u, a_all, lp);

        const float x = fmaf(rx, Wf, ox) - 0.5f;
        const float y = fmaf(ry, Wf, oy) - 0.5f;
        const float x0f = floorf(x), y0f = floorf(y);
        const int   x0 = (int)x0f,  y0 = (int)y0f;
        const float fx = x - x0f,   fy = y - y0f;

#pragma unroll
        for (int dy = 0; dy < 2; dy++) {
            const int  yi = y0 + dy;
            const bool vy = (yi >= 0) && (yi < Wl);
            const int  yc = min(max(yi, 0), Wl - 1);
            const float wy = (dy ? fy : 1.f - fy) * a;
#pragma unroll
            for (int dx = 0; dx < 2; dx++) {
                const int  xi = x0 + dx;
                const bool vx = (xi >= 0) && (xi < Wl);
                const int  xc = min(max(xi, 0), Wl - 1);
                const float w = (vx && vy) ? (dx ? fx : 1.f - fx) * wy : 0.f;

                const uint4 raw = __ldg((const uint4*)&valb[(size_t)(yc * Wl + xc) * 32]);
                const float2 f0 = __half22float2(*(const __half2*)&raw.x);
                const float2 f1 = __half22float2(*(const __half2*)&raw.y);
                const float2 f2 = __half22float2(*(const __half2*)&raw.z);
                const float2 f3 = __half22float2(*(const __half2*)&raw.w);
                acc[0] = fmaf(w, f0.x, acc[0]);
                acc[1] = fmaf(w, f0.y, acc[1]);
                acc[2] = fmaf(w, f1.x, acc[2]);
                acc[3] = fmaf(w, f1.y, acc[3]);
                acc[4] = fmaf(w, f2.x, acc[4]);
                acc[5] = fmaf(w, f2.y, acc[5]);
                acc[6] = fmaf(w, f3.x, acc[6]);
                acc[7] = fmaf(w, f3.y, acc[7]);
            }
        }
    }

#pragma unroll
    for (int d = 4; d <= 16; d <<= 1)
#pragma unroll
        for (int i = 0; i < 8; i++)
            acc[i] += __shfl_xor_sync(~0u, acc[i], d);

    if (lane < 4) {
        const size_t o = (size_t)m * CDIM + head * DHEAD + c4 * 8;
        __half2 h0 = __floats2half2_rn(acc[0], acc[1]);
        __half2 h1 = __floats2half2_rn(acc[2], acc[3]);
        __half2 h2 = __floats2half2_rn(acc[4], acc[5]);
        __half2 h3 = __floats2half2_rn(acc[6], acc[7]);
        uint4 pk;
        pk.x = *(uint32_t*)&h0; pk.y = *(uint32_t*)&h1;
        pk.z = *(uint32_t*)&h2; pk.w = *(uint32_t*)&h3;
        *(uint4*)&sout[o] = pk;
    }
}

// ---------------------------------------------------------------------------
// Launch
// ---------------------------------------------------------------------------
extern "C" void kernel_launch(void* const* d_in, const int* in_sizes, int n_in,
                              void* d_out, int out_size)
{
    const float* query  = (const float*)d_in[0];
    const float* value  = (const float*)d_in[1];
    const float* refpts = (const float*)d_in[2];
    const float* W_off  = (const float*)d_in[4];
    const float* b_off  = (const float*)d_in[5];
    const float* W_attn = (const float*)d_in[6];
    const float* b_attn = (const float*)d_in[7];
    const float* W_v    = (const float*)d_in[8];
    const float* b_v    = (const float*)d_in[9];
    const float* W_out  = (const float*)d_in[10];
    const float* b_out  = (const float*)d_in[11];
    float* out = (float*)d_out;

    __half *tab, *v16, *q16, *s16;
    float *oa, *bias_oa;
    cudaGetSymbolAddress((void**)&tab,  g_tab);
    cudaGetSymbolAddress((void**)&oa,   g_oa);
    cudaGetSymbolAddress((void**)&v16,  g_v16);
    cudaGetSymbolAddress((void**)&q16,  g_q16);
    cudaGetSymbolAddress((void**)&s16,  g_s16);
    cudaGetSymbolAddress((void**)&bias_oa, g_bias_oa);
    __half *wvh, *wvl, *oah, *oal, *wuh, *wul;
    cudaGetSymbolAddress((void**)&wvh, g_wv_hi); cudaGetSymbolAddress((void**)&wvl, g_wv_lo);
    cudaGetSymbolAddress((void**)&oah, g_oa_hi); cudaGetSymbolAddress((void**)&oal, g_oa_lo);
    cudaGetSymbolAddress((void**)&wuh, g_wu_hi); cudaGetSymbolAddress((void**)&wul, g_wu_lo);

    cudaFuncSetAttribute(mma_gemm,     cudaFuncAttributeMaxDynamicSharedMemorySize, GEMM_SMEM_BYTES);
    cudaFuncSetAttribute(mma_gemm_tab, cudaFuncAttributeMaxDynamicSharedMemorySize, GEMM_SMEM_BYTES);

    // L0: weight transpose + hi/lo split + bias concat
    prep_weights<<<dim3(NOA, 3), 256>>>(W_v, W_off, W_attn, W_out, b_off, b_attn,
                                        wvh, wvl, oah, oal, wuh, wul, bias_oa);
    // L1: value/query fp32 -> fp16
    {
        int n4 = MROWS * CDIM / 4;
        to_half_kernel<<<dim3((n4 + 255) / 256, 2), 256>>>(value, query, v16, q16, n4);
    }

    dim3 blk(256);
    dim3 gridV(MROWS / 128, 2);    // N=256
    dim3 gridOA(MROWS / 128, 3);   // N=384

    // L2: value projection -> head-sliced fp16 table (dedicated kernel)
    mma_gemm_tab<<<gridV, blk, GEMM_SMEM_BYTES>>>(v16, wvh, wvl, b_v, tab);
    // L3: offsets + attn logits (fused, N=384)
    mma_gemm<<<gridOA, blk, GEMM_SMEM_BYTES>>>(q16, oah, oal, bias_oa, oa, NOA);
    // L4: sampler -> fp16 (512-thread blocks, 2 queries each)
    sample_kernel<<<dim3(QLEN / 2, BS), 512>>>(tab, oa, refpts, s16);
    // L5: output projection
    mma_gemm<<<gridV, blk, GEMM_SMEM_BYTES>>>(s16, wuh, wul, b_out, out, 256);
}

// round 16
// speedup vs baseline: 1.3432x; 1.0520x over previous
#include <cuda_runtime.h>
#include <cuda_fp16.h>
#include <cstdint>
#include <math.h>

// ---------------------------------------------------------------------------
// Problem constants
// ---------------------------------------------------------------------------
#define BS      2
#define QLEN    21760            // 128^2 + 64^2 + 32^2 + 16^2
#define MROWS   (BS * QLEN)      // 43520
#define CDIM    256
#define HEADS   8
#define DHEAD   32
#define LEVELS  4
#define POINTS  4
#define NOA     384              // concat: 256 offsets + 128 attn logits

// ---------------------------------------------------------------------------
// Scratch (static device globals)
// ---------------------------------------------------------------------------
__device__ __half g_val_h[MROWS * CDIM];      // value @ W_v + b_v (fp16 table, [m][c])
__device__ float  g_oa  [MROWS * NOA];        // [m][0:256]=offsets, [256:384]=logits
__device__ __half g_v16 [MROWS * CDIM];       // value fp16 (GEMM A)
__device__ __half g_q16 [MROWS * CDIM];       // query fp16 (GEMM A)
__device__ __half g_s16 [MROWS * CDIM];       // sampled fp16 (GEMM A)

// Transposed weights [N, K=256] fp16 hi/lo
__device__ __half g_wv_hi [CDIM * CDIM], g_wv_lo [CDIM * CDIM];
__device__ __half g_oa_hi [NOA  * CDIM], g_oa_lo [NOA  * CDIM];
__device__ __half g_wu_hi [CDIM * CDIM], g_wu_lo [CDIM * CDIM];
__device__ float  g_bias_oa[NOA];

// ---------------------------------------------------------------------------
// Helpers
// ---------------------------------------------------------------------------
__device__ __forceinline__ uint32_t smem_u32(const void* p) {
    uint32_t a;
    asm("{ .reg .u64 t; cvta.to.shared.u64 t, %1; cvt.u32.u64 %0, t; }" : "=r"(a) : "l"(p));
    return a;
}
#define SMEM_SWZ64(off) ((off) ^ (((off) >> 3) & 0x30))

__device__ __forceinline__ void ldsm4(uint32_t& r0, uint32_t& r1, uint32_t& r2, uint32_t& r3,
                                      uint32_t addr) {
    asm volatile("ldmatrix.sync.aligned.m8n8.x4.shared.b16 {%0,%1,%2,%3}, [%4];"
                 : "=r"(r0), "=r"(r1), "=r"(r2), "=r"(r3) : "r"(addr));
}
__device__ __forceinline__ void mma_f16(float* d, const uint32_t* a, const uint32_t* b) {
    asm volatile(
        "mma.sync.aligned.m16n8k16.row.col.f32.f16.f16.f32 "
        "{%0,%1,%2,%3}, {%4,%5,%6,%7}, {%8,%9}, {%0,%1,%2,%3};"
        : "+f"(d[0]), "+f"(d[1]), "+f"(d[2]), "+f"(d[3])
        : "r"(a[0]), "r"(a[1]), "r"(a[2]), "r"(a[3]), "r"(b[0]), "r"(b[1]));
}
#define CP_ASYNC16(dst_u32, src_ptr) \
    asm volatile("cp.async.cg.shared.global [%0], [%1], 16;" :: "r"(dst_u32), "l"(src_ptr))
#define CP_COMMIT()  asm volatile("cp.async.commit_group;" ::: "memory")
#define CP_WAIT1()   asm volatile("cp.async.wait_group 1;" ::: "memory")
#define CP_WAIT0()   asm volatile("cp.async.wait_group 0;" ::: "memory")

// ---------------------------------------------------------------------------
// Prep: fp32 -> fp16 conversion for value & query (GEMM A operands)
// ---------------------------------------------------------------------------
__global__ void to_half_kernel(const float* __restrict__ value,
                               const float* __restrict__ query,
                               __half* __restrict__ vh, __half* __restrict__ qh, int n4)
{
    int i = blockIdx.x * blockDim.x + threadIdx.x;
    if (i >= n4) return;
    const float* x = blockIdx.y ? query : value;
    __half* o = blockIdx.y ? qh : vh;
    float4 v = ((const float4*)x)[i];
    __half2 h01 = __floats2half2_rn(v.x, v.y);
    __half2 h23 = __floats2half2_rn(v.z, v.w);
    uint2 pk; pk.x = *(uint32_t*)&h01; pk.y = *(uint32_t*)&h23;
    ((uint2*)o)[i] = pk;
}

// Weights: transpose + fp16 hi/lo split. which=0: W_v, 1: [W_off|W_attn], 2: W_out
__global__ void prep_weights(const float* __restrict__ Wv,
                             const float* __restrict__ Woff,
                             const float* __restrict__ Wattn,
                             const float* __restrict__ Wout,
                             const float* __restrict__ b_off,
                             const float* __restrict__ b_attn,
                             __half* __restrict__ vh, __half* __restrict__ vl,
                             __half* __restrict__ oh, __half* __restrict__ ol,
                             __half* __restrict__ uh, __half* __restrict__ ul,
                             float* __restrict__ bias_oa)
{
    const int which = blockIdx.y;
    const int n = blockIdx.x;
    const int k = threadIdx.x;
    float v; __half *th, *tl;
    if (which == 0) {
        if (n >= CDIM) return;
        v = Wv[k * CDIM + n]; th = vh; tl = vl;
    } else if (which == 1) {
        v = (n < 256) ? Woff[k * 256 + n] : Wattn[k * 128 + (n - 256)];
        th = oh; tl = ol;
        if (k == 0) bias_oa[n] = (n < 256) ? b_off[n] : b_attn[n - 256];
    } else {
        if (n >= CDIM) return;
        v = Wout[k * CDIM + n]; th = uh; tl = ul;
    }
    __half h = __float2half_rn(v);
    th[n * 256 + k] = h;
    tl[n * 256 + k] = __float2half_rn(v - __half2float(h));
}

// ---------------------------------------------------------------------------
// GEMM building blocks (R13-proven): 2-pass hi/lo fp16, CTA 128x128, K=32
// chunks, 3-stage cp.async, SW64 smem.
// ---------------------------------------------------------------------------
#define STAGE_BYTES 24576
#define GEMM_SMEM_BYTES (3 * STAGE_BYTES)

#define LOAD_STAGE(cc, buf) do {                                                   \
    const uint32_t st = sb + (buf) * STAGE_BYTES;                                  \
    const int kc = (cc) * 32;                                                      \
    _Pragma("unroll")                                                              \
    for (int it = 0; it < 2; it++) {                                               \
        int idx = it * 256 + tid;                                                  \
        int row = idx >> 2, seg = idx & 3;                                         \
        uint32_t so = SMEM_SWZ64((uint32_t)(row * 64 + seg * 16));                 \
        size_t ga = (size_t)(mtile + row) * 256 + kc + seg * 8;                    \
        size_t gb = (size_t)(ntile + row) * 256 + kc + seg * 8;                    \
        CP_ASYNC16(st + so,         A  + ga);                                      \
        CP_ASYNC16(st + 8192 + so,  Bh + gb);                                      \
        CP_ASYNC16(st + 16384 + so, Bl + gb);                                      \
    }                                                                              \
} while (0)

#define GEMM_MAIN_LOOP()                                                           \
    float acc[2][8][4];                                                            \
    _Pragma("unroll")                                                              \
    for (int i = 0; i < 2; i++)                                                    \
        _Pragma("unroll")                                                          \
        for (int j = 0; j < 8; j++)                                                \
            _Pragma("unroll")                                                      \
            for (int k = 0; k < 4; k++) acc[i][j][k] = 0.f;                        \
    const int a_row = wm * 32 + (lane & 7) + ((lane >> 3) & 1) * 8;                \
    const int a_sg  = (lane >> 4);                                                 \
    const int b_row = wn * 64 + (lane & 7) + (lane >> 4) * 8;                      \
    const int b_sg  = ((lane >> 3) & 1);                                           \
    LOAD_STAGE(0, 0); CP_COMMIT();                                                 \
    LOAD_STAGE(1, 1); CP_COMMIT();                                                 \
    int cbuf = 0;                                                                  \
    _Pragma("unroll 1")                                                            \
    for (int c = 0; c < 8; c++) {                                                  \
        if (c < 7) CP_WAIT1(); else CP_WAIT0();                                    \
        __syncthreads();                                                           \
        if (c < 6) {                                                               \
            const int lbuf = (cbuf + 2 >= 3) ? cbuf + 2 - 3 : cbuf + 2;            \
            LOAD_STAGE(c + 2, lbuf);                                               \
            CP_COMMIT();                                                           \
        }                                                                          \
        const uint32_t st  = sb + cbuf * STAGE_BYTES;                              \
        const uint32_t sA = st, sBh = st + 8192, sBl = st + 16384;                 \
        _Pragma("unroll")                                                          \
        for (int ks = 0; ks < 2; ks++) {                                           \
            uint32_t a[2][4];                                                      \
            _Pragma("unroll")                                                      \
            for (int mt = 0; mt < 2; mt++) {                                       \
                uint32_t off = SMEM_SWZ64((uint32_t)((a_row + mt * 16) * 64 +      \
                                                     (a_sg + ks * 2) * 16));       \
                ldsm4(a[mt][0], a[mt][1], a[mt][2], a[mt][3], sA + off);           \
            }                                                                      \
            _Pragma("unroll")                                                      \
            for (int nt2 = 0; nt2 < 4; nt2++) {                                    \
                uint32_t off = SMEM_SWZ64((uint32_t)((b_row + nt2 * 16) * 64 +     \
                                                     (b_sg + ks * 2) * 16));       \
                uint32_t bh[4], bl[4];                                             \
                ldsm4(bh[0], bh[1], bh[2], bh[3], sBh + off);                      \
                ldsm4(bl[0], bl[1], bl[2], bl[3], sBl + off);                      \
                _Pragma("unroll")                                                  \
                for (int mt = 0; mt < 2; mt++)                                     \
                    _Pragma("unroll")                                              \
                    for (int half = 0; half < 2; half++) {                         \
                        float* a4 = acc[mt][nt2 * 2 + half];                       \
                        mma_f16(a4, a[mt], &bh[half * 2]);                         \
                        mma_f16(a4, a[mt], &bl[half * 2]);                         \
                    }                                                              \
            }                                                                      \
        }                                                                          \
        cbuf = (cbuf + 1 >= 3) ? 0 : cbuf + 1;                                     \
    }

// Fused launch: value projection (y<2, fp16 table out) + OA GEMM (y>=2, fp32 out).
__global__ __launch_bounds__(256, 2)
void mma_gemm_fused(const __half* __restrict__ v16, const __half* __restrict__ q16,
                    const __half* __restrict__ wvh, const __half* __restrict__ wvl,
                    const __half* __restrict__ oah, const __half* __restrict__ oal,
                    const float* __restrict__ b_v, const float* __restrict__ bias_oa,
                    __half* __restrict__ valh, float* __restrict__ oa)
{
    extern __shared__ char smem[];
    const uint32_t sb = smem_u32(smem);
    const int tid  = threadIdx.x;
    const int lane = tid & 31;
    const int wid  = tid >> 5;
    const int wm   = wid & 3;
    const int wn   = wid >> 2;
    const int mtile = blockIdx.x * 128;

    const int  yb    = blockIdx.y;
    const bool isVal = (yb < 2);
    const int  ntile = (isVal ? yb : yb - 2) * 128;
    const __half* A  = isVal ? v16 : q16;
    const __half* Bh = isVal ? wvh : oah;
    const __half* Bl = isVal ? wvl : oal;
    const float* bias = isVal ? b_v : bias_oa;

    GEMM_MAIN_LOOP()

    if (isVal) {
#pragma unroll
        for (int mt = 0; mt < 2; mt++) {
            const int r0 = mtile + wm * 32 + mt * 16 + (lane >> 2);
#pragma unroll
            for (int nt = 0; nt < 8; nt++) {
                const int cc = ntile + wn * 64 + nt * 8 + (lane & 3) * 2;
                const float bx = __ldg(bias + cc), by = __ldg(bias + cc + 1);
                __half2 h0 = __floats2half2_rn(acc[mt][nt][0] + bx, acc[mt][nt][1] + by);
                __half2 h1 = __floats2half2_rn(acc[mt][nt][2] + bx, acc[mt][nt][3] + by);
                *(__half2*)&valh[(size_t)r0       * CDIM + cc] = h0;
                *(__half2*)&valh[(size_t)(r0 + 8) * CDIM + cc] = h1;
            }
        }
    } else {
#pragma unroll
        for (int mt = 0; mt < 2; mt++) {
            const int r0 = mtile + wm * 32 + mt * 16 + (lane >> 2);
#pragma unroll
            for (int nt = 0; nt < 8; nt++) {
                const int cc = ntile + wn * 64 + nt * 8 + (lane & 3) * 2;
                const float bx = __ldg(bias + cc), by = __ldg(bias + cc + 1);
                float2 o0 = {acc[mt][nt][0] + bx, acc[mt][nt][1] + by};
                float2 o1 = {acc[mt][nt][2] + bx, acc[mt][nt][3] + by};
                *(float2*)&oa[(size_t)r0       * NOA + cc] = o0;
                *(float2*)&oa[(size_t)(r0 + 8) * NOA + cc] = o1;
            }
        }
    }
}

// Output projection GEMM (fp32 out + bias), R13 form.
__global__ __launch_bounds__(256, 2)
void mma_gemm(const __half* __restrict__ A,
              const __half* __restrict__ Bh, const __half* __restrict__ Bl,
              const float* __restrict__ bias, float* __restrict__ C, int Ncols)
{
    extern __shared__ char smem[];
    const uint32_t sb = smem_u32(smem);
    const int tid  = threadIdx.x;
    const int lane = tid & 31;
    const int wid  = tid >> 5;
    const int wm   = wid & 3;
    const int wn   = wid >> 2;
    const int mtile = blockIdx.x * 128;
    const int ntile = blockIdx.y * 128;

    GEMM_MAIN_LOOP()

#pragma unroll
    for (int mt = 0; mt < 2; mt++) {
        const int r0 = mtile + wm * 32 + mt * 16 + (lane >> 2);
#pragma unroll
        for (int nt = 0; nt < 8; nt++) {
            const int cc = ntile + wn * 64 + nt * 8 + (lane & 3) * 2;
            const float bx = __ldg(bias + cc), by = __ldg(bias + cc + 1);
            float2 o0 = {acc[mt][nt][0] + bx, acc[mt][nt][1] + by};
            float2 o1 = {acc[mt][nt][2] + bx, acc[mt][nt][3] + by};
            *(float2*)&C[(size_t)r0       * Ncols + cc] = o0;
            *(float2*)&C[(size_t)(r0 + 8) * Ncols + cc] = o1;
        }
    }
}
#undef LOAD_STAGE

// ---------------------------------------------------------------------------
// Deformable sampling v3 (R13-proven): warp = head; lane -> (group g = lane>>2,
// octet c4 = lane&3). 8 groups process 8 corners per warp-instruction; lane
// gathers 8 channels via LDG.128. 512-thread blocks: 2 queries per block.
// ---------------------------------------------------------------------------
__global__ __launch_bounds__(512)
void sample_kernel(const __half* __restrict__ valh,
                   const float* __restrict__ oa,
                   const float* __restrict__ ref,
                   __half* __restrict__ sout)
{
    const int q    = blockIdx.x * 2 + (threadIdx.x >> 8);
    const int b    = blockIdx.y;
    const int m    = b * QLEN + q;
    const int tid  = threadIdx.x & 255;
    const int head = tid >> 5;
    const int lane = threadIdx.x & 31;
    const int g    = lane >> 2;        // 8 groups of 4 lanes
    const int c4   = lane & 3;         // channel octet
    const int l    = g >> 1;           // level
    const int h    = g & 1;            // point-half

    // --- softmax over this head's 16 logits ---
    const float* row = oa + (size_t)m * NOA;
    float lg = __ldg(&row[256 + head * 16 + (lane & 15)]);
    float mx = lg;
#pragma unroll
    for (int d = 1; d < 16; d <<= 1) mx = fmaxf(mx, __shfl_xor_sync(~0u, mx, d));
    float e = __expf(lg - mx);
    float s = e;
#pragma unroll
    for (int d = 1; d < 16; d <<= 1) s += __shfl_xor_sync(~0u, s, d);
    const float a_all = e / s;

    const float ov = __ldg(&row[head * 32 + lane]);
    const float rv = __ldg(&ref[(size_t)m * (LEVELS * 2) + (lane & 7)]);

    const int   Wl = 128 >> l;
    const float Wf = (float)Wl;
    const int   start = (65536 - (65536 >> (2 * l))) / 3;

    const float rx = __shfl_sync(~0u, rv, 2 * l);
    const float ry = __shfl_sync(~0u, rv, 2 * l + 1);

    const __half* valb = valh + ((size_t)b * QLEN + start) * CDIM + head * DHEAD + c4 * 8;

    float acc[8];
#pragma unroll
    for (int i = 0; i < 8; i++) acc[i] = 0.f;

#pragma unroll
    for (int j = 0; j < 2; j++) {
        const int lp = l * 4 + h * 2 + j;
        const float ox = __shfl_sync(~0u, ov, 2 * lp);
        const float oy = __shfl_sync(~0u, ov, 2 * lp + 1);
        const float a  = __shfl_sync(~0u, a_all, lp);

        const float x = fmaf(rx, Wf, ox) - 0.5f;
        const float y = fmaf(ry, Wf, oy) - 0.5f;
        const float x0f = floorf(x), y0f = floorf(y);
        const int   x0 = (int)x0f,  y0 = (int)y0f;
        const float fx = x - x0f,   fy = y - y0f;

#pragma unroll
        for (int dy = 0; dy < 2; dy++) {
            const int  yi = y0 + dy;
            const bool vy = (yi >= 0) && (yi < Wl);
            const int  yc = min(max(yi, 0), Wl - 1);
            const float wy = (dy ? fy : 1.f - fy) * a;
#pragma unroll
            for (int dx = 0; dx < 2; dx++) {
                const int  xi = x0 + dx;
                const bool vx = (xi >= 0) && (xi < Wl);
                const int  xc = min(max(xi, 0), Wl - 1);
                const float w = (vx && vy) ? (dx ? fx : 1.f - fx) * wy : 0.f;

                const uint4 raw = __ldg((const uint4*)&valb[(size_t)(yc * Wl + xc) * CDIM]);
                const float2 f0 = __half22float2(*(const __half2*)&raw.x);
                const float2 f1 = __half22float2(*(const __half2*)&raw.y);
                const float2 f2 = __half22float2(*(const __half2*)&raw.z);
                const float2 f3 = __half22float2(*(const __half2*)&raw.w);
                acc[0] = fmaf(w, f0.x, acc[0]);
                acc[1] = fmaf(w, f0.y, acc[1]);
                acc[2] = fmaf(w, f1.x, acc[2]);
                acc[3] = fmaf(w, f1.y, acc[3]);
                acc[4] = fmaf(w, f2.x, acc[4]);
                acc[5] = fmaf(w, f2.y, acc[5]);
                acc[6] = fmaf(w, f3.x, acc[6]);
                acc[7] = fmaf(w, f3.y, acc[7]);
            }
        }
    }

#pragma unroll
    for (int d = 4; d <= 16; d <<= 1)
#pragma unroll
        for (int i = 0; i < 8; i++)
            acc[i] += __shfl_xor_sync(~0u, acc[i], d);

    if (lane < 4) {
        const size_t o = (size_t)m * CDIM + head * DHEAD + c4 * 8;
        __half2 h0 = __floats2half2_rn(acc[0], acc[1]);
        __half2 h1 = __floats2half2_rn(acc[2], acc[3]);
        __half2 h2 = __floats2half2_rn(acc[4], acc[5]);
        __half2 h3 = __floats2half2_rn(acc[6], acc[7]);
        uint4 pk;
        pk.x = *(uint32_t*)&h0; pk.y = *(uint32_t*)&h1;
        pk.z = *(uint32_t*)&h2; pk.w = *(uint32_t*)&h3;
        *(uint4*)&sout[o] = pk;
    }
}

// ---------------------------------------------------------------------------
// Launch
// ---------------------------------------------------------------------------
extern "C" void kernel_launch(void* const* d_in, const int* in_sizes, int n_in,
                              void* d_out, int out_size)
{
    const float* query  = (const float*)d_in[0];
    const float* value  = (const float*)d_in[1];
    const float* refpts = (const float*)d_in[2];
    const float* W_off  = (const float*)d_in[4];
    const float* b_off  = (const float*)d_in[5];
    const float* W_attn = (const float*)d_in[6];
    const float* b_attn = (const float*)d_in[7];
    const float* W_v    = (const float*)d_in[8];
    const float* b_v    = (const float*)d_in[9];
    const float* W_out  = (const float*)d_in[10];
    const float* b_out  = (const float*)d_in[11];
    float* out = (float*)d_out;

    __half *valh, *v16, *q16, *s16;
    float *oa, *bias_oa;
    cudaGetSymbolAddress((void**)&valh, g_val_h);
    cudaGetSymbolAddress((void**)&oa,   g_oa);
    cudaGetSymbolAddress((void**)&v16,  g_v16);
    cudaGetSymbolAddress((void**)&q16,  g_q16);
    cudaGetSymbolAddress((void**)&s16,  g_s16);
    cudaGetSymbolAddress((void**)&bias_oa, g_bias_oa);
    __half *wvh, *wvl, *oah, *oal, *wuh, *wul;
    cudaGetSymbolAddress((void**)&wvh, g_wv_hi); cudaGetSymbolAddress((void**)&wvl, g_wv_lo);
    cudaGetSymbolAddress((void**)&oah, g_oa_hi); cudaGetSymbolAddress((void**)&oal, g_oa_lo);
    cudaGetSymbolAddress((void**)&wuh, g_wu_hi); cudaGetSymbolAddress((void**)&wul, g_wu_lo);

    cudaFuncSetAttribute(mma_gemm_fused, cudaFuncAttributeMaxDynamicSharedMemorySize, GEMM_SMEM_BYTES);
    cudaFuncSetAttribute(mma_gemm,       cudaFuncAttributeMaxDynamicSharedMemorySize, GEMM_SMEM_BYTES);

    // L0: weight transpose + hi/lo split + bias concat
    prep_weights<<<dim3(NOA, 3), 256>>>(W_v, W_off, W_attn, W_out, b_off, b_attn,
                                        wvh, wvl, oah, oal, wuh, wul, bias_oa);
    // L1: value/query fp32 -> fp16
    {
        int n4 = MROWS * CDIM / 4;
        to_half_kernel<<<dim3((n4 + 255) / 256, 2), 256>>>(value, query, v16, q16, n4);
    }

    dim3 blk(256);

    // L2: fused value-projection + OA GEMM (1700 CTAs, one dispatch)
    mma_gemm_fused<<<dim3(MROWS / 128, 5), blk, GEMM_SMEM_BYTES>>>(
        v16, q16, wvh, wvl, oah, oal, b_v, bias_oa, valh, oa);
    // L3: sampler -> fp16 (512-thread blocks, 2 queries each)
    sample_kernel<<<dim3(QLEN / 2, BS), 512>>>(valh, oa, refpts, s16);
    // L4: output projection
    mma_gemm<<<dim3(MROWS / 128, 2), blk, GEMM_SMEM_BYTES>>>(s16, wuh, wul, b_out, out, 256);
}